// round 8
// baseline (speedup 1.0000x reference)
#include <cuda_runtime.h>
#include <cstdint>

#define N_TOTAL   4096
#define NN_NODES  1024
#define NN_MARB   3072
#define NN_EATERS 64
#define EPS_F     1e-6f
#define NWARPS    16

#define ADD_F32X2(out, a, b) \
    asm("add.rn.f32x2 %0, %1, %2;" : "=l"(out) : "l"(a), "l"(b))
#define MUL_F32X2(out, a, b) \
    asm("mul.rn.f32x2 %0, %1, %2;" : "=l"(out) : "l"(a), "l"(b))
#define FMA_F32X2(out, a, b, c) \
    asm("fma.rn.f32x2 %0, %1, %2, %3;" : "=l"(out) : "l"(a), "l"(b), "l"(c))
#define PACK_F32X2(out, lo, hi) \
    asm("mov.b64 %0, {%1, %2};" : "=l"(out) : "f"(lo), "f"(hi))
#define UNPACK_F32X2(lo, hi, in) \
    asm("mov.b64 {%0, %1}, %2;" : "=f"(lo), "=f"(hi) : "l"(in))

__device__ __forceinline__ float rsqrt_fast(float x) {
    float r;
    asm("rsqrt.approx.f32 %0, %1;" : "=f"(r) : "f"(x));
    return r;
}

// Producer/consumer handshake for fused eaten computation.
__device__ int g_ready = 0;   // incremented by the 32 node blocks
__device__ int g_done  = 0;   // incremented by the 96 marble blocks; last resets

// 128 blocks x 512 threads (16 warps). Block b owns bodies [b*32, b*32+32)
// (one per lane, replicated across all 16 warps). j-loop runs over 2 shared
// tiles of 2048 bodies in 4-body groups: per group one LDS.128 per 2 bodies
// for (x,x,y,y) + one LDS.128 for 4 masses -> 3 MIO loads + 4 MUFU per
// 4 bodies (was 5 MIO per 2). fma work per pair unchanged.
__global__ __launch_bounds__(512, 1)
void nbody_fused_kernel(const float* __restrict__ pos,
                        const float* __restrict__ vel,
                        const float* __restrict__ mass,
                        const int*   __restrict__ eidx,
                        const float* __restrict__ erad,
                        const float* __restrict__ dtp,
                        float* __restrict__ out) {
    __shared__ float4 sh_xy[1024];   // pair p: (x_{2p}, x_{2p+1}, y_{2p}, y_{2p+1})  16 KB
    __shared__ float4 sh_m[512];     // group g: (m_{4g}..m_{4g+3})                    8 KB
    __shared__ float2 spart[NWARPS][32];
    __shared__ float  s_ex[NN_EATERS], s_ey[NN_EATERS], s_er2[NN_EATERS];
    __shared__ int    s_eidx[NN_EATERS];

    const int tid  = threadIdx.x;
    const int lane = tid & 31;
    const int warp = tid >> 5;
    const int blk  = blockIdx.x;
    const int i    = blk * 32 + lane;
    const bool is_marble_blk = (blk >= 32);

    if (is_marble_blk && tid < NN_EATERS) {
        s_eidx[tid] = eidx[tid];
        float r = erad[tid];
        s_er2[tid] = r * r;
    }

    const float2 p = ((const float2*)pos)[i];

    uint64_t npx2, npy2, eps2;
    PACK_F32X2(npx2, -p.x, -p.x);
    PACK_F32X2(npy2, -p.y, -p.y);
    PACK_F32X2(eps2, EPS_F, EPS_F);

    uint64_t AX, AY, BX, BY;          // two accumulator sets (chains A/B)
    PACK_F32X2(AX, 0.0f, 0.0f);
    AY = AX;  BX = AX;  BY = AX;

    #pragma unroll
    for (int tile = 0; tile < 2; tile++) {
        // Fill: 1024 xy-pairs (2/thread) + 512 mass-groups (1/thread).
        #pragma unroll
        for (int k = 0; k < 2; k++) {
            const int pj = k * 512 + tid;
            const int gp = tile * 1024 + pj;
            float4 v = ((const float4*)pos)[gp];        // (x0,y0,x1,y1)
            sh_xy[pj] = make_float4(v.x, v.z, v.y, v.w);
        }
        sh_m[tid & 511] = ((const float4*)mass)[tile * 512 + (tid & 511)];
        __syncthreads();

        const int base = warp * 32;                     // 32 groups of 4 bodies
        #pragma unroll 4
        for (int g = 0; g < 32; g++) {
            const float4 xyA = sh_xy[(base + g) * 2];     // LDS.128
            const float4 xyB = sh_xy[(base + g) * 2 + 1]; // LDS.128
            const float4 mm  = sh_m[base + g];            // LDS.128
            // ---- chain A: bodies 4g, 4g+1 ----
            {
                uint64_t qx, qy, qm, DX, DY, S, R, R2, W;
                PACK_F32X2(qx, xyA.x, xyA.y);
                PACK_F32X2(qy, xyA.z, xyA.w);
                PACK_F32X2(qm, mm.x, mm.y);
                ADD_F32X2(DX, qx, npx2);
                ADD_F32X2(DY, qy, npy2);
                FMA_F32X2(S, DX, DX, eps2);
                FMA_F32X2(S, DY, DY, S);
                float s0, s1;
                UNPACK_F32X2(s0, s1, S);
                float r0 = rsqrt_fast(s0);
                float r1 = rsqrt_fast(s1);
                PACK_F32X2(R, r0, r1);
                MUL_F32X2(R2, R, R);
                MUL_F32X2(W, R, qm);
                MUL_F32X2(W, W, R2);                   // m_j * (d2+eps)^-1.5
                // Coincident pair (incl. j==i): DX=DY=0 -> contributes 0.
                FMA_F32X2(AX, W, DX, AX);
                FMA_F32X2(AY, W, DY, AY);
            }
            // ---- chain B: bodies 4g+2, 4g+3 ----
            {
                uint64_t qx, qy, qm, DX, DY, S, R, R2, W;
                PACK_F32X2(qx, xyB.x, xyB.y);
                PACK_F32X2(qy, xyB.z, xyB.w);
                PACK_F32X2(qm, mm.z, mm.w);
                ADD_F32X2(DX, qx, npx2);
                ADD_F32X2(DY, qy, npy2);
                FMA_F32X2(S, DX, DX, eps2);
                FMA_F32X2(S, DY, DY, S);
                float s0, s1;
                UNPACK_F32X2(s0, s1, S);
                float r0 = rsqrt_fast(s0);
                float r1 = rsqrt_fast(s1);
                PACK_F32X2(R, r0, r1);
                MUL_F32X2(R2, R, R);
                MUL_F32X2(W, R, qm);
                MUL_F32X2(W, W, R2);
                FMA_F32X2(BX, W, DX, BX);
                FMA_F32X2(BY, W, DY, BY);
            }
        }
        __syncthreads();
    }

    {
        float a0, a1, b0, b1, c0, c1, d0, d1;
        UNPACK_F32X2(a0, a1, AX);
        UNPACK_F32X2(b0, b1, AY);
        UNPACK_F32X2(c0, c1, BX);
        UNPACK_F32X2(d0, d1, BY);
        spart[warp][lane] = make_float2((a0 + a1) + (c0 + c1),
                                        (b0 + b1) + (d0 + d1));
    }
    __syncthreads();

    float nx = 0.0f, ny = 0.0f;
    if (warp == 0) {
        float fx = 0.0f, fy = 0.0f;
        #pragma unroll
        for (int w = 0; w < NWARPS; w++) {
            fx += spart[w][lane].x;
            fy += spart[w][lane].y;
        }
        const float dt = dtp[0];
        const float vx = vel[2 * i]     + fx * dt;
        const float vy = vel[2 * i + 1] + fy * dt;
        nx = p.x + vx * dt;
        ny = p.y + vy * dt;
        // state_new = stack([pos_new, vel_new]) : pos block first, then vel.
        out[2 * i]                   = nx;
        out[2 * i + 1]               = ny;
        out[2 * N_TOTAL + 2 * i]     = vx;
        out[2 * N_TOTAL + 2 * i + 1] = vy;
    }

    if (!is_marble_blk) {
        __threadfence();
        __syncthreads();
        if (tid == 0) atomicAdd(&g_ready, 1);
        return;
    }

    // ---- Marble block: fused eaten computation ----
    if (tid == 0) {
        while (*((volatile int*)&g_ready) < 32) { /* node blocks never wait */ }
    }
    __syncthreads();
    __threadfence();

    if (tid < NN_EATERS) {
        int e = s_eidx[tid];
        s_ex[tid] = __ldcg(&out[2 * e]);
        s_ey[tid] = __ldcg(&out[2 * e + 1]);
    }
    __syncthreads();

    if (warp == 0) {
        int eaten = 0;
        #pragma unroll
        for (int k = 0; k < NN_EATERS; k++) {
            float dx = nx - s_ex[k];
            float dy = ny - s_ey[k];
            float d2 = fmaf(dx, dx, dy * dy);
            eaten |= (d2 <= s_er2[k]);
        }
        const int m = i - NN_NODES;
        out[4 * N_TOTAL + m] = eaten ? 1.0f : 0.0f;
    }
    __syncthreads();

    if (tid == 0) {
        int d = atomicAdd(&g_done, 1);
        if (d == 95) {
            g_done  = 0;
            __threadfence();
            g_ready = 0;
        }
    }
}

extern "C" void kernel_launch(void* const* d_in, const int* in_sizes, int n_in,
                              void* d_out, int out_size) {
    const float* positions  = (const float*)d_in[0];
    const float* velocities = (const float*)d_in[1];
    const float* masses     = (const float*)d_in[2];
    const int*   eater_idx  = (const int*)  d_in[3];
    const float* eater_rad  = (const float*)d_in[4];
    const float* dt         = (const float*)d_in[5];
    float* out = (float*)d_out;

    nbody_fused_kernel<<<N_TOTAL / 32, 512>>>(positions, velocities, masses,
                                              eater_idx, eater_rad, dt, out);
}

// round 9
// speedup vs baseline: 1.0019x; 1.0019x over previous
#include <cuda_runtime.h>
#include <cstdint>

#define N_TOTAL   4096
#define NN_NODES  1024
#define NN_MARB   3072
#define NN_EATERS 64
#define EPS_F     1e-6f
#define NWARPS    16

__device__ __forceinline__ float rsqrt_fast(float x) {
    float r;
    asm("rsqrt.approx.f32 %0, %1;" : "=f"(r) : "f"(x));
    return r;
}

// Producer/consumer handshake for fused eaten computation.
__device__ int g_ready = 0;   // incremented by the 32 node blocks
__device__ int g_done  = 0;   // incremented by the 96 marble blocks; last resets

// 128 blocks x 512 threads (16 warps). Block b owns bodies [b*32, b*32+32)
// (one per lane, replicated across all 16 warps). Each warp accumulates a
// disjoint 128-body j-slice per tile; 2 tiles of 2048 float4 (x,y,m,0).
// Scalar math: 9 fma-pipe ops + 1 MUFU + 1 LDS.128 per pair, no packs.
__global__ __launch_bounds__(512, 1)
void nbody_fused_kernel(const float* __restrict__ pos,
                        const float* __restrict__ vel,
                        const float* __restrict__ mass,
                        const int*   __restrict__ eidx,
                        const float* __restrict__ erad,
                        const float* __restrict__ dtp,
                        float* __restrict__ out) {
    __shared__ float4 sh[2048];                 // (x, y, m, 0)   32 KB
    __shared__ float2 spart[NWARPS][32];
    __shared__ float  s_ex[NN_EATERS], s_ey[NN_EATERS], s_er2[NN_EATERS];
    __shared__ int    s_eidx[NN_EATERS];

    const int tid  = threadIdx.x;
    const int lane = tid & 31;
    const int warp = tid >> 5;
    const int blk  = blockIdx.x;
    const int i    = blk * 32 + lane;
    const bool is_marble_blk = (blk >= 32);

    if (is_marble_blk && tid < NN_EATERS) {
        s_eidx[tid] = eidx[tid];
        float r = erad[tid];
        s_er2[tid] = r * r;
    }

    const float2 p = ((const float2*)pos)[i];
    const float px = p.x, py = p.y;

    float ax = 0.0f, ay = 0.0f;

    #pragma unroll
    for (int tile = 0; tile < 2; tile++) {
        // Cooperative fill: 2048 bodies, 4 per thread.
        #pragma unroll
        for (int k = 0; k < 4; k++) {
            const int j  = k * 512 + tid;
            const int gj = tile * 2048 + j;
            float2 q = ((const float2*)pos)[gj];
            sh[j] = make_float4(q.x, q.y, mass[gj], 0.0f);
        }
        __syncthreads();

        const int base = warp * 128;            // 128 bodies per warp
        #pragma unroll 8
        for (int jj = 0; jj < 128; jj++) {
            const float4 q = sh[base + jj];     // LDS.128, warp-uniform
            const float dx = q.x - px;
            const float dy = q.y - py;
            const float d2 = fmaf(dx, dx, fmaf(dy, dy, EPS_F));
            const float r  = rsqrt_fast(d2);    // MUFU.RSQ
            const float r2 = r * r;
            const float mr = r * q.z;
            const float w  = r2 * mr;           // m_j * (d2+eps)^-1.5
            // Coincident pair (incl. j==i): dx=dy=0 -> contributes 0,
            // matching the reference's masked inv_d3.
            ax = fmaf(w, dx, ax);
            ay = fmaf(w, dy, ay);
        }
        __syncthreads();
    }

    spart[warp][lane] = make_float2(ax, ay);
    __syncthreads();

    float nx = 0.0f, ny = 0.0f;
    if (warp == 0) {
        float fx = 0.0f, fy = 0.0f;
        #pragma unroll
        for (int w = 0; w < NWARPS; w++) {
            fx += spart[w][lane].x;
            fy += spart[w][lane].y;
        }
        const float dt = dtp[0];
        const float vx = vel[2 * i]     + fx * dt;
        const float vy = vel[2 * i + 1] + fy * dt;
        nx = px + vx * dt;
        ny = py + vy * dt;
        // state_new = stack([pos_new, vel_new]) : pos block first, then vel.
        out[2 * i]                   = nx;
        out[2 * i + 1]               = ny;
        out[2 * N_TOTAL + 2 * i]     = vx;
        out[2 * N_TOTAL + 2 * i + 1] = vy;
    }

    if (!is_marble_blk) {
        // Release: syncthreads orders warp0's stores before tid0's fence+add.
        __syncthreads();
        if (tid == 0) {
            __threadfence();
            atomicAdd(&g_ready, 1);
        }
        return;
    }

    // ---- Marble block: fused eaten computation ----
    if (tid == 0) {
        // Low-traffic spin: only 96 threads chip-wide, with sleep backoff.
        while (*((volatile int*)&g_ready) < 32) {
            __nanosleep(100);
        }
        __threadfence();                        // acquire
    }
    __syncthreads();

    if (tid < NN_EATERS) {
        int e = s_eidx[tid];                    // node index (< 1024)
        s_ex[tid] = __ldcg(&out[2 * e]);        // L2 read (skip stale L1)
        s_ey[tid] = __ldcg(&out[2 * e + 1]);
    }
    __syncthreads();

    if (warp == 0) {
        int eaten = 0;
        #pragma unroll
        for (int k = 0; k < NN_EATERS; k++) {
            float dx = nx - s_ex[k];
            float dy = ny - s_ey[k];
            float d2 = fmaf(dx, dx, dy * dy);
            eaten |= (d2 <= s_er2[k]);
        }
        const int m = i - NN_NODES;             // marble index 0..3071
        out[4 * N_TOTAL + m] = eaten ? 1.0f : 0.0f;
    }
    __syncthreads();

    // Last marble block resets the handshake for the next graph replay.
    if (tid == 0) {
        int d = atomicAdd(&g_done, 1);
        if (d == 95) {
            g_done = 0;
            __threadfence();
            g_ready = 0;
        }
    }
}

extern "C" void kernel_launch(void* const* d_in, const int* in_sizes, int n_in,
                              void* d_out, int out_size) {
    const float* positions  = (const float*)d_in[0];
    const float* velocities = (const float*)d_in[1];
    const float* masses     = (const float*)d_in[2];
    const int*   eater_idx  = (const int*)  d_in[3];
    const float* eater_rad  = (const float*)d_in[4];
    const float* dt         = (const float*)d_in[5];
    float* out = (float*)d_out;

    nbody_fused_kernel<<<N_TOTAL / 32, 512>>>(positions, velocities, masses,
                                              eater_idx, eater_rad, dt, out);
}

// round 10
// speedup vs baseline: 1.0152x; 1.0133x over previous
#include <cuda_runtime.h>
#include <cstdint>

#define N_TOTAL   4096
#define NN_NODES  1024
#define NN_MARB   3072
#define NN_EATERS 64
#define EPS_F     1e-6f
#define NWARPS    16

__device__ __forceinline__ float rsqrt_fast(float x) {
    float r;
    asm("rsqrt.approx.f32 %0, %1;" : "=f"(r) : "f"(x));
    return r;
}

// 128 blocks x 512 threads (16 warps). Block b owns bodies [b*32, b*32+32)
// (one per lane, replicated across all 16 warps). Each warp accumulates a
// disjoint 128-body j-slice per tile; 2 tiles of 2048 float4 (x,y,m,0).
// Scalar math: 9 fma-pipe ops + 1 MUFU + 1 LDS.128 per pair.
__global__ __launch_bounds__(512, 1)
void nbody_kernel(const float* __restrict__ pos,
                  const float* __restrict__ vel,
                  const float* __restrict__ mass,
                  const float* __restrict__ dtp,
                  float* __restrict__ out) {
    __shared__ float4 sh[2048];                 // (x, y, m, 0)   32 KB
    __shared__ float2 spart[NWARPS][32];

    const int tid  = threadIdx.x;
    const int lane = tid & 31;
    const int warp = tid >> 5;
    const int i    = blockIdx.x * 32 + lane;

    const float2 p = ((const float2*)pos)[i];
    const float px = p.x, py = p.y;

    float ax = 0.0f, ay = 0.0f;

    #pragma unroll
    for (int tile = 0; tile < 2; tile++) {
        // Cooperative fill: 2048 bodies, 4 per thread.
        #pragma unroll
        for (int k = 0; k < 4; k++) {
            const int j  = k * 512 + tid;
            const int gj = tile * 2048 + j;
            float2 q = ((const float2*)pos)[gj];
            sh[j] = make_float4(q.x, q.y, mass[gj], 0.0f);
        }
        __syncthreads();

        const int base = warp * 128;            // 128 bodies per warp
        #pragma unroll 8
        for (int jj = 0; jj < 128; jj++) {
            const float4 q = sh[base + jj];     // LDS.128, warp-uniform
            const float dx = q.x - px;
            const float dy = q.y - py;
            const float d2 = fmaf(dx, dx, fmaf(dy, dy, EPS_F));
            const float r  = rsqrt_fast(d2);    // MUFU.RSQ
            const float r2 = r * r;
            const float mr = r * q.z;
            const float w  = r2 * mr;           // m_j * (d2+eps)^-1.5
            // Coincident pair (incl. j==i): dx=dy=0 -> contributes 0,
            // matching the reference's masked inv_d3.
            ax = fmaf(w, dx, ax);
            ay = fmaf(w, dy, ay);
        }
        __syncthreads();
    }

    spart[warp][lane] = make_float2(ax, ay);
    __syncthreads();

    if (warp == 0) {
        float fx = 0.0f, fy = 0.0f;
        #pragma unroll
        for (int w = 0; w < NWARPS; w++) {
            fx += spart[w][lane].x;
            fy += spart[w][lane].y;
        }
        const float dt = dtp[0];
        const float vx = vel[2 * i]     + fx * dt;
        const float vy = vel[2 * i + 1] + fy * dt;
        const float nx = px + vx * dt;
        const float ny = py + vy * dt;
        // state_new = stack([pos_new, vel_new]) : pos block first, then vel.
        out[2 * i]                   = nx;
        out[2 * i + 1]               = ny;
        out[2 * N_TOTAL + 2 * i]     = vx;
        out[2 * N_TOTAL + 2 * i + 1] = vy;
    }
}

// 6 blocks x 512 threads: one thread per marble.
__global__ __launch_bounds__(512, 1)
void eaten_kernel(const int* __restrict__ eidx,
                  const float* __restrict__ erad,
                  float* __restrict__ out) {
    __shared__ float ex[NN_EATERS], ey[NN_EATERS], er2[NN_EATERS];
    const int tid = threadIdx.x;
    if (tid < NN_EATERS) {
        int e = eidx[tid];                 // index into nodes (< 1024)
        ex[tid] = out[2 * e];              // pos_new[e].x
        ey[tid] = out[2 * e + 1];
        float r = erad[tid];
        er2[tid] = r * r;
    }
    __syncthreads();

    const int m = blockIdx.x * blockDim.x + tid;   // marble 0..3071
    const float2 mp = ((const float2*)out)[NN_NODES + m];
    int eaten = 0;
    #pragma unroll
    for (int k = 0; k < NN_EATERS; k++) {
        float dx = mp.x - ex[k];
        float dy = mp.y - ey[k];
        float d2 = fmaf(dx, dx, dy * dy);
        eaten |= (d2 <= er2[k]);
    }
    out[4 * N_TOTAL + m] = eaten ? 1.0f : 0.0f;
}

extern "C" void kernel_launch(void* const* d_in, const int* in_sizes, int n_in,
                              void* d_out, int out_size) {
    const float* positions  = (const float*)d_in[0];
    const float* velocities = (const float*)d_in[1];
    const float* masses     = (const float*)d_in[2];
    const int*   eater_idx  = (const int*)  d_in[3];
    const float* eater_rad  = (const float*)d_in[4];
    const float* dt         = (const float*)d_in[5];
    float* out = (float*)d_out;

    nbody_kernel<<<N_TOTAL / 32, 512>>>(positions, velocities, masses, dt, out);
    eaten_kernel<<<NN_MARB / 512, 512>>>(eater_idx, eater_rad, out);
}